// round 12
// baseline (speedup 1.0000x reference)
#include <cuda_runtime.h>
#include <cuda_fp16.h>
#include <cstdint>

// ============================================================================
// out[T,D] = X[T,D] @ (W_shared + W_expert)^T + bias
// (reference MoE collapses exactly; see R0 analysis)
// R12: eliminate the 14.6us xcvt pass. GEMM ingests X as fp32 via cp.async
//      (proven path), A-fragments via LDS.64 + cvt.rn.f16x2.f32 (R3-proven
//      A-path shape). B stays fp16 ldmatrix from pre-summed g_Wch.
//      BM=BN=128, NST=3, 2 CTAs/SM, mma.sync m16n8k16 fp16.
// ============================================================================

#define D_DIM   1024
#define T_DIM   16384
#define BM      128
#define BN      128
#define BK      32
#define NST     3
#define THREADS 256
#define APADF   36                          // f32 per A row (32 + 4 pad), 144B
#define APADH   40                          // f16 per B row (32 + 8 pad), 80B
#define A_FLOATS (BM * APADF)               // 4608  (18432 B)
#define B_HALVES (BN * APADH)               // 5120  (10240 B)
#define A_BYTES  (A_FLOATS * 4)
#define B_BYTES  (B_HALVES * 2)
#define STAGE_BYTES (A_BYTES + B_BYTES)     // 28672
#define SMEM_BYTES  (NST * STAGE_BYTES)     // 86016 -> 2 CTAs/SM (172KB)

__device__ __half g_Wch[(size_t)D_DIM * D_DIM];  // fp16 (Ws+We) (2MB)

// ---------------------------------------------------------------- helpers
static __device__ __forceinline__ uint32_t smem_u32(const void* p) {
    uint32_t a;
    asm("{ .reg .u64 t; cvta.to.shared.u64 t, %1; cvt.u32.u64 %0, t; }"
        : "=r"(a) : "l"(p));
    return a;
}

static __device__ __forceinline__ void cp16(uint32_t dst, const void* src) {
    asm volatile("cp.async.cg.shared.global [%0], [%1], 16;" :: "r"(dst), "l"(src));
}

static __device__ __forceinline__ uint32_t h2u(__half2 h) {
    uint32_t u;
    __builtin_memcpy(&u, &h, 4);
    return u;
}

// pack two f32 -> f16x2 (lo = first/lower-k element), round-to-nearest
static __device__ __forceinline__ uint32_t cvt2h(float2 p) {
    uint32_t u;
    asm("cvt.rn.f16x2.f32 %0, %1, %2;" : "=r"(u) : "f"(p.y), "f"(p.x));
    return u;
}

static __device__ __forceinline__ void ldm4(uint32_t* r, uint32_t addr) {
    asm volatile("ldmatrix.sync.aligned.m8n8.x4.shared.b16 {%0,%1,%2,%3}, [%4];"
        : "=r"(r[0]), "=r"(r[1]), "=r"(r[2]), "=r"(r[3]) : "r"(addr));
}

static __device__ __forceinline__ void mma16(float* d, const uint32_t* a, const uint32_t* b) {
    asm volatile(
        "mma.sync.aligned.m16n8k16.row.col.f32.f16.f16.f32 "
        "{%0,%1,%2,%3}, {%4,%5,%6,%7}, {%8,%9}, {%0,%1,%2,%3};"
        : "+f"(d[0]), "+f"(d[1]), "+f"(d[2]), "+f"(d[3])
        : "r"(a[0]), "r"(a[1]), "r"(a[2]), "r"(a[3]), "r"(b[0]), "r"(b[1]));
}

// ---------------------------------------------------------------- pre-kernel
__global__ void wsum_kernel(const float* __restrict__ Ws, const float* __restrict__ We) {
    size_t i = (size_t)blockIdx.x * blockDim.x + threadIdx.x;   // over float4
    float4 a = ((const float4*)Ws)[i];
    float4 b = ((const float4*)We)[i];
    uint2 o;
    o.x = h2u(__floats2half2_rn(a.x + b.x, a.y + b.y));
    o.y = h2u(__floats2half2_rn(a.z + b.z, a.w + b.w));
    ((uint2*)g_Wch)[i] = o;
}

// ---------------------------------------------------------------- GEMM
__global__ void __launch_bounds__(THREADS, 2)
moe_gemm_kernel(const float* __restrict__ X, const float* __restrict__ bias,
                float* __restrict__ Out)
{
    extern __shared__ char smc[];
    float* smA = (float*)smc;                        // per-stage A at stage*STAGE_BYTES
    const int tid  = threadIdx.x;
    const int lane = tid & 31, wid = tid >> 5;
    const int wm = wid >> 2, wn = wid & 3;          // 2 x 4 warps, 64x32 tiles
    const int g = lane >> 2, t = lane & 3;

    // 8 consecutive CTAs share one A (X) tile -> L2 reuse of X
    const int m0 = (blockIdx.x >> 3) * BM;
    const int n0 = (blockIdx.x & 7) * BN;

    const uint32_t sbase = smem_u32(smc);

    // ldmatrix lane-constant offsets (B only)
    const int brow = (lane >> 4) * 8 + (lane & 7);
    const int bkh  = ((lane >> 3) & 1) * 8;

    float acc[4][4][4];
#pragma unroll
    for (int mi = 0; mi < 4; mi++)
#pragma unroll
        for (int ni = 0; ni < 4; ni++)
#pragma unroll
            for (int j = 0; j < 4; j++) acc[mi][ni][j] = 0.0f;

    auto load_chunk = [&](int st, int c) {
        const float*  xb = X + (size_t)m0 * D_DIM + c * BK;
        const __half* wb = g_Wch + (size_t)n0 * D_DIM + c * BK;
        uint32_t ab = sbase + st * STAGE_BYTES;
        uint32_t bb = ab + A_BYTES;
#pragma unroll
        for (int i = 0; i < 4; i++) {   // A: 128 rows x 8 segs of 4 f32 (16B)
            int idx = tid + i * THREADS;
            int row = idx >> 3, seg = idx & 7;
            cp16(ab + (row * APADF + seg * 4) * 4, xb + (size_t)row * D_DIM + seg * 4);
        }
#pragma unroll
        for (int i = 0; i < 2; i++) {   // B: 128 rows x 4 segs of 8 f16 (16B)
            int idx = tid + i * THREADS;
            int row = idx >> 2, seg = idx & 3;
            cp16(bb + (row * APADH + seg * 8) * 2, wb + (size_t)row * D_DIM + seg * 8);
        }
    };

    // prologue: chunks 0,1
#pragma unroll
    for (int s = 0; s < NST - 1; s++) {
        load_chunk(s, s);
        asm volatile("cp.async.commit_group;" ::: "memory");
    }

    const int NCHUNK = D_DIM / BK;                   // 32
    for (int c = 0; c < NCHUNK; c++) {
        const int st = c % NST;
        asm volatile("cp.async.wait_group 1;" ::: "memory");
        __syncthreads();

        const float*   a_s = (const float*)(smc + st * STAGE_BYTES);
        const uint32_t bB  = sbase + st * STAGE_BYTES + A_BYTES;

#pragma unroll
        for (int ks = 0; ks < 2; ks++) {             // 2 x k=16 steps
            const int k0 = ks * 16 + 2 * t;
            uint32_t af[4][4];
#pragma unroll
            for (int mi = 0; mi < 4; mi++) {
                const int r0 = wm * 64 + mi * 16 + g;
                // m16n8k16 A frag: (g,k0..k0+1), (g+8,k0..), (g,k0+8..), (g+8,k0+8..)
                af[mi][0] = cvt2h(*(const float2*)(a_s + r0 * APADF + k0));
                af[mi][1] = cvt2h(*(const float2*)(a_s + (r0 + 8) * APADF + k0));
                af[mi][2] = cvt2h(*(const float2*)(a_s + r0 * APADF + k0 + 8));
                af[mi][3] = cvt2h(*(const float2*)(a_s + (r0 + 8) * APADF + k0 + 8));
            }
            uint32_t bf[4][2];
#pragma unroll
            for (int p = 0; p < 2; p++) {            // 2 n-pairs of 16 rows
                uint32_t r4[4];
                ldm4(r4, bB + (((wn * 32 + p * 16 + brow) * APADH)
                               + ks * 16 + bkh) * 2);
                bf[p * 2 + 0][0] = r4[0];  bf[p * 2 + 0][1] = r4[1];
                bf[p * 2 + 1][0] = r4[2];  bf[p * 2 + 1][1] = r4[3];
            }
#pragma unroll
            for (int mi = 0; mi < 4; mi++)
#pragma unroll
                for (int ni = 0; ni < 4; ni++)
                    mma16(acc[mi][ni], af[mi], bf[ni]);
        }

        // refill stage (c+2)%3 (chunk c-1's stage; all warps passed barrier)
        int nc = c + NST - 1;
        if (nc < NCHUNK) load_chunk(nc % NST, nc);
        asm volatile("cp.async.commit_group;" ::: "memory");  // uniform count
    }

    // ---- epilogue: add bias, store fp32, coalesced float2
#pragma unroll
    for (int mi = 0; mi < 4; mi++) {
        int row = m0 + wm * 64 + mi * 16 + g;
        float* o0 = Out + (size_t)row * D_DIM;
        float* o1 = o0 + (size_t)8 * D_DIM;
#pragma unroll
        for (int ni = 0; ni < 4; ni++) {
            int col = n0 + wn * 32 + ni * 8 + 2 * t;
            float2 bv = *(const float2*)(bias + col);
            float2 v0, v1;
            v0.x = acc[mi][ni][0] + bv.x;  v0.y = acc[mi][ni][1] + bv.y;
            v1.x = acc[mi][ni][2] + bv.x;  v1.y = acc[mi][ni][3] + bv.y;
            *(float2*)(o0 + col) = v0;
            *(float2*)(o1 + col) = v1;
        }
    }
    (void)smA;
}

// ---------------------------------------------------------------- launch
extern "C" void kernel_launch(void* const* d_in, const int* in_sizes, int n_in,
                              void* d_out, int out_size)
{
    const float* x    = (const float*)d_in[0];  // (4,4096,1024)
    const float* Ws   = (const float*)d_in[3];  // (1024,1024)
    const float* We   = (const float*)d_in[4];  // (1024,1024)
    const float* bias = (const float*)d_in[6];  // (1024,)
    float* out = (float*)d_out;

    cudaFuncSetAttribute(moe_gemm_kernel,
                         cudaFuncAttributeMaxDynamicSharedMemorySize, SMEM_BYTES);

    // Wc = fp16(Ws + We)
    wsum_kernel<<<(D_DIM * (D_DIM / 4)) / 256, 256>>>(Ws, We);

    // GEMM: (16384/128) m-tiles x (1024/128) n-tiles = 1024 CTAs
    moe_gemm_kernel<<<(T_DIM / BM) * (D_DIM / BN), THREADS, SMEM_BYTES>>>(x, bias, out);
}

// round 13
// speedup vs baseline: 1.5878x; 1.5878x over previous
#include <cuda_runtime.h>
#include <cuda_fp16.h>
#include <cstdint>

// ============================================================================
// out[T,D] = X[T,D] @ (W_shared + W_expert)^T + bias
// (reference MoE collapses exactly; see R0 analysis)
// R13: GEMM = byte-exact R11 (mma.sync fp16 ceiling; all in-GEMM-conversion
//      variants falsified in R9/R12). Pre-pass: single fused launch, 16B
//      stores (X->fp16 + fp16(Ws+We)).
// ============================================================================

#define D_DIM   1024
#define T_DIM   16384
#define BM      128
#define BN      128
#define BK      32
#define NST     4
#define THREADS 256
#define APADH   40                          // halves per row (32 + 8 pad), 80B
#define A_HALVES (BM * APADH)               // 5120
#define B_HALVES (BN * APADH)               // 5120
#define STAGE_HALVES (A_HALVES + B_HALVES)  // 10240
#define SMEM_BYTES (NST * STAGE_HALVES * 2) // 81920

#define XBLOCKS 8192                        // X: 16M elems / (8/thread * 256)

__device__ __half g_Xh[(size_t)T_DIM * D_DIM];   // fp16 X (32MB)
__device__ __half g_Wch[(size_t)D_DIM * D_DIM];  // fp16 (Ws+We) (2MB)

// ---------------------------------------------------------------- helpers
static __device__ __forceinline__ uint32_t smem_u32(const void* p) {
    uint32_t a;
    asm("{ .reg .u64 t; cvta.to.shared.u64 t, %1; cvt.u32.u64 %0, t; }"
        : "=r"(a) : "l"(p));
    return a;
}

static __device__ __forceinline__ void cp16(uint32_t dst, const void* src) {
    asm volatile("cp.async.cg.shared.global [%0], [%1], 16;" :: "r"(dst), "l"(src));
}

static __device__ __forceinline__ uint32_t h2u(__half2 h) {
    uint32_t u;
    __builtin_memcpy(&u, &h, 4);
    return u;
}

static __device__ __forceinline__ void ldm4(uint32_t* r, uint32_t addr) {
    asm volatile("ldmatrix.sync.aligned.m8n8.x4.shared.b16 {%0,%1,%2,%3}, [%4];"
        : "=r"(r[0]), "=r"(r[1]), "=r"(r[2]), "=r"(r[3]) : "r"(addr));
}

static __device__ __forceinline__ void mma16(float* d, const uint32_t* a, const uint32_t* b) {
    asm volatile(
        "mma.sync.aligned.m16n8k16.row.col.f32.f16.f16.f32 "
        "{%0,%1,%2,%3}, {%4,%5,%6,%7}, {%8,%9}, {%0,%1,%2,%3};"
        : "+f"(d[0]), "+f"(d[1]), "+f"(d[2]), "+f"(d[3])
        : "r"(a[0]), "r"(a[1]), "r"(a[2]), "r"(a[3]), "r"(b[0]), "r"(b[1]));
}

// ---------------------------------------------------------------- pre-pass
// blocks [0, XBLOCKS): X -> fp16, 8 elems/thread, one 16B store.
// blocks [XBLOCKS, XBLOCKS+512): Wc = fp16(Ws + We), 8 elems/thread.
__global__ void cvt_kernel(const float* __restrict__ X,
                           const float* __restrict__ Ws,
                           const float* __restrict__ We)
{
    if (blockIdx.x < XBLOCKS) {
        size_t i = (size_t)blockIdx.x * 256 + threadIdx.x;   // uint4 index
        float4 v0 = ((const float4*)X)[2 * i];
        float4 v1 = ((const float4*)X)[2 * i + 1];
        uint4 o;
        o.x = h2u(__floats2half2_rn(v0.x, v0.y));
        o.y = h2u(__floats2half2_rn(v0.z, v0.w));
        o.z = h2u(__floats2half2_rn(v1.x, v1.y));
        o.w = h2u(__floats2half2_rn(v1.z, v1.w));
        ((uint4*)g_Xh)[i] = o;
    } else {
        size_t i = (size_t)(blockIdx.x - XBLOCKS) * 256 + threadIdx.x;
        float4 a0 = ((const float4*)Ws)[2 * i];
        float4 a1 = ((const float4*)Ws)[2 * i + 1];
        float4 b0 = ((const float4*)We)[2 * i];
        float4 b1 = ((const float4*)We)[2 * i + 1];
        uint4 o;
        o.x = h2u(__floats2half2_rn(a0.x + b0.x, a0.y + b0.y));
        o.y = h2u(__floats2half2_rn(a0.z + b0.z, a0.w + b0.w));
        o.z = h2u(__floats2half2_rn(a1.x + b1.x, a1.y + b1.y));
        o.w = h2u(__floats2half2_rn(a1.z + b1.z, a1.w + b1.w));
        ((uint4*)g_Wch)[i] = o;
    }
}

// ---------------------------------------------------------------- GEMM (R11)
__global__ void __launch_bounds__(THREADS, 2)
moe_gemm_kernel(const float* __restrict__ bias, float* __restrict__ Out)
{
    extern __shared__ __half sm[];
    const int tid  = threadIdx.x;
    const int lane = tid & 31, wid = tid >> 5;
    const int wm = wid >> 2, wn = wid & 3;          // 2 x 4 warps, 64x32 tiles
    const int g = lane >> 2, t = lane & 3;

    // 8 consecutive CTAs share one A (X) tile -> L2 reuse of X
    const int m0 = (blockIdx.x >> 3) * BM;
    const int n0 = (blockIdx.x & 7) * BN;

    const uint32_t sbase = smem_u32(sm);

    // ldmatrix lane-constant offsets
    const int arow = ((lane >> 3) & 1) * 8 + (lane & 7);
    const int akh  = (lane >> 4) * 8;
    const int brow = (lane >> 4) * 8 + (lane & 7);
    const int bkh  = ((lane >> 3) & 1) * 8;

    float acc[4][4][4];
#pragma unroll
    for (int mi = 0; mi < 4; mi++)
#pragma unroll
        for (int ni = 0; ni < 4; ni++)
#pragma unroll
            for (int j = 0; j < 4; j++) acc[mi][ni][j] = 0.0f;

    auto load_chunk = [&](int st, int c) {
        const __half* xb = g_Xh + (size_t)m0 * D_DIM + c * BK;
        const __half* wb = g_Wch + (size_t)n0 * D_DIM + c * BK;
        uint32_t ab = sbase + (st * STAGE_HALVES) * 2;
        uint32_t bb = ab + A_HALVES * 2;
#pragma unroll
        for (int i = 0; i < 2; i++) {   // A: 128 rows x 4 segs of 8 halves
            int idx = tid + i * THREADS;
            int row = idx >> 2, seg = idx & 3;
            cp16(ab + (row * APADH + seg * 8) * 2, xb + (size_t)row * D_DIM + seg * 8);
        }
#pragma unroll
        for (int i = 0; i < 2; i++) {   // B: 128 rows x 4 segs
            int idx = tid + i * THREADS;
            int row = idx >> 2, seg = idx & 3;
            cp16(bb + (row * APADH + seg * 8) * 2, wb + (size_t)row * D_DIM + seg * 8);
        }
    };

    // prologue: chunks 0,1,2
#pragma unroll
    for (int s = 0; s < NST - 1; s++) {
        load_chunk(s, s);
        asm volatile("cp.async.commit_group;" ::: "memory");
    }

    const int NCHUNK = D_DIM / BK;                   // 32
    for (int c = 0; c < NCHUNK; c++) {
        const int st = c & (NST - 1);
        asm volatile("cp.async.wait_group 2;" ::: "memory");
        __syncthreads();

        const uint32_t aB = sbase + (st * STAGE_HALVES) * 2;
        const uint32_t bB = aB + A_HALVES * 2;

#pragma unroll
        for (int ks = 0; ks < 2; ks++) {             // 2 x k=16 steps
            uint32_t af[4][4];
#pragma unroll
            for (int mi = 0; mi < 4; mi++)
                ldm4(af[mi], aB + (((wm * 64 + mi * 16 + arow) * APADH)
                                   + ks * 16 + akh) * 2);
            uint32_t bf[4][2];
#pragma unroll
            for (int p = 0; p < 2; p++) {            // 2 n-pairs of 16 rows
                uint32_t r4[4];
                ldm4(r4, bB + (((wn * 32 + p * 16 + brow) * APADH)
                               + ks * 16 + bkh) * 2);
                bf[p * 2 + 0][0] = r4[0];  bf[p * 2 + 0][1] = r4[1];
                bf[p * 2 + 1][0] = r4[2];  bf[p * 2 + 1][1] = r4[3];
            }
#pragma unroll
            for (int mi = 0; mi < 4; mi++)
#pragma unroll
                for (int ni = 0; ni < 4; ni++)
                    mma16(acc[mi][ni], af[mi], bf[ni]);
        }

        // refill stage (c+3)&3 (chunk c-1's stage; compute done in all warps)
        int nc = c + NST - 1;
        if (nc < NCHUNK) load_chunk(nc & (NST - 1), nc);
        asm volatile("cp.async.commit_group;" ::: "memory");  // uniform count
    }

    // ---- epilogue: add bias, store fp32, coalesced float2
#pragma unroll
    for (int mi = 0; mi < 4; mi++) {
        int row = m0 + wm * 64 + mi * 16 + g;
        float* o0 = Out + (size_t)row * D_DIM;
        float* o1 = o0 + (size_t)8 * D_DIM;
#pragma unroll
        for (int ni = 0; ni < 4; ni++) {
            int col = n0 + wn * 32 + ni * 8 + 2 * t;
            float2 bv = *(const float2*)(bias + col);
            float2 v0, v1;
            v0.x = acc[mi][ni][0] + bv.x;  v0.y = acc[mi][ni][1] + bv.y;
            v1.x = acc[mi][ni][2] + bv.x;  v1.y = acc[mi][ni][3] + bv.y;
            *(float2*)(o0 + col) = v0;
            *(float2*)(o1 + col) = v1;
        }
    }
}

// ---------------------------------------------------------------- launch
extern "C" void kernel_launch(void* const* d_in, const int* in_sizes, int n_in,
                              void* d_out, int out_size)
{
    const float* x    = (const float*)d_in[0];  // (4,4096,1024)
    const float* Ws   = (const float*)d_in[3];  // (1024,1024)
    const float* We   = (const float*)d_in[4];  // (1024,1024)
    const float* bias = (const float*)d_in[6];  // (1024,)
    float* out = (float*)d_out;

    cudaFuncSetAttribute(moe_gemm_kernel,
                         cudaFuncAttributeMaxDynamicSharedMemorySize, SMEM_BYTES);

    // fused pre-pass: X -> fp16 (blocks 0..8191), Wc = fp16(Ws+We) (last 512)
    cvt_kernel<<<XBLOCKS + 512, 256>>>(x, Ws, We);

    // GEMM: (16384/128) m-tiles x (1024/128) n-tiles = 1024 CTAs
    moe_gemm_kernel<<<(T_DIM / BM) * (D_DIM / BN), THREADS, SMEM_BYTES>>>(bias, out);
}

// round 14
// speedup vs baseline: 1.6987x; 1.0699x over previous
#include <cuda_runtime.h>
#include <cuda_fp16.h>
#include <cstdint>

// ============================================================================
// out[T,D] = X[T,D] @ (W_shared + W_expert)^T + bias
// (reference MoE collapses exactly; see R0 analysis)
// R14: BK 32->64 to amortize the fixed per-chunk barrier bubble (tensor=53%
//      with ~1024 MAC/cyc/SM mma.sync ceiling => bubble-bound, not rate-bound).
//      NST=3, APADH=72, 108KB smem, still 2 CTAs/SM. Pre-pass = R13 fused cvt.
// ============================================================================

#define D_DIM   1024
#define T_DIM   16384
#define BM      128
#define BN      128
#define BK      64
#define NST     3
#define THREADS 256
#define APADH   72                          // halves per row (64 + 8 pad), 144B
#define A_HALVES (BM * APADH)               // 9216
#define B_HALVES (BN * APADH)               // 9216
#define STAGE_HALVES (A_HALVES + B_HALVES)  // 18432
#define SMEM_BYTES (NST * STAGE_HALVES * 2) // 110592

#define XBLOCKS 8192                        // X: 16M elems / (8/thread * 256)

__device__ __half g_Xh[(size_t)T_DIM * D_DIM];   // fp16 X (32MB)
__device__ __half g_Wch[(size_t)D_DIM * D_DIM];  // fp16 (Ws+We) (2MB)

// ---------------------------------------------------------------- helpers
static __device__ __forceinline__ uint32_t smem_u32(const void* p) {
    uint32_t a;
    asm("{ .reg .u64 t; cvta.to.shared.u64 t, %1; cvt.u32.u64 %0, t; }"
        : "=r"(a) : "l"(p));
    return a;
}

static __device__ __forceinline__ void cp16(uint32_t dst, const void* src) {
    asm volatile("cp.async.cg.shared.global [%0], [%1], 16;" :: "r"(dst), "l"(src));
}

static __device__ __forceinline__ uint32_t h2u(__half2 h) {
    uint32_t u;
    __builtin_memcpy(&u, &h, 4);
    return u;
}

static __device__ __forceinline__ void ldm4(uint32_t* r, uint32_t addr) {
    asm volatile("ldmatrix.sync.aligned.m8n8.x4.shared.b16 {%0,%1,%2,%3}, [%4];"
        : "=r"(r[0]), "=r"(r[1]), "=r"(r[2]), "=r"(r[3]) : "r"(addr));
}

static __device__ __forceinline__ void mma16(float* d, const uint32_t* a, const uint32_t* b) {
    asm volatile(
        "mma.sync.aligned.m16n8k16.row.col.f32.f16.f16.f32 "
        "{%0,%1,%2,%3}, {%4,%5,%6,%7}, {%8,%9}, {%0,%1,%2,%3};"
        : "+f"(d[0]), "+f"(d[1]), "+f"(d[2]), "+f"(d[3])
        : "r"(a[0]), "r"(a[1]), "r"(a[2]), "r"(a[3]), "r"(b[0]), "r"(b[1]));
}

// ---------------------------------------------------------------- pre-pass
// blocks [0, XBLOCKS): X -> fp16, 8 elems/thread, one 16B store.
// blocks [XBLOCKS, XBLOCKS+512): Wc = fp16(Ws + We), 8 elems/thread.
__global__ void cvt_kernel(const float* __restrict__ X,
                           const float* __restrict__ Ws,
                           const float* __restrict__ We)
{
    if (blockIdx.x < XBLOCKS) {
        size_t i = (size_t)blockIdx.x * 256 + threadIdx.x;   // uint4 index
        float4 v0 = ((const float4*)X)[2 * i];
        float4 v1 = ((const float4*)X)[2 * i + 1];
        uint4 o;
        o.x = h2u(__floats2half2_rn(v0.x, v0.y));
        o.y = h2u(__floats2half2_rn(v0.z, v0.w));
        o.z = h2u(__floats2half2_rn(v1.x, v1.y));
        o.w = h2u(__floats2half2_rn(v1.z, v1.w));
        ((uint4*)g_Xh)[i] = o;
    } else {
        size_t i = (size_t)(blockIdx.x - XBLOCKS) * 256 + threadIdx.x;
        float4 a0 = ((const float4*)Ws)[2 * i];
        float4 a1 = ((const float4*)Ws)[2 * i + 1];
        float4 b0 = ((const float4*)We)[2 * i];
        float4 b1 = ((const float4*)We)[2 * i + 1];
        uint4 o;
        o.x = h2u(__floats2half2_rn(a0.x + b0.x, a0.y + b0.y));
        o.y = h2u(__floats2half2_rn(a0.z + b0.z, a0.w + b0.w));
        o.z = h2u(__floats2half2_rn(a1.x + b1.x, a1.y + b1.y));
        o.w = h2u(__floats2half2_rn(a1.z + b1.z, a1.w + b1.w));
        ((uint4*)g_Wch)[i] = o;
    }
}

// ---------------------------------------------------------------- GEMM
__global__ void __launch_bounds__(THREADS, 2)
moe_gemm_kernel(const float* __restrict__ bias, float* __restrict__ Out)
{
    extern __shared__ __half sm[];
    const int tid  = threadIdx.x;
    const int lane = tid & 31, wid = tid >> 5;
    const int wm = wid >> 2, wn = wid & 3;          // 2 x 4 warps, 64x32 tiles
    const int g = lane >> 2, t = lane & 3;

    // 8 consecutive CTAs share one A (X) tile -> L2 reuse of X
    const int m0 = (blockIdx.x >> 3) * BM;
    const int n0 = (blockIdx.x & 7) * BN;

    const uint32_t sbase = smem_u32(sm);

    // ldmatrix lane-constant offsets
    const int arow = ((lane >> 3) & 1) * 8 + (lane & 7);
    const int akh  = (lane >> 4) * 8;
    const int brow = (lane >> 4) * 8 + (lane & 7);
    const int bkh  = ((lane >> 3) & 1) * 8;

    float acc[4][4][4];
#pragma unroll
    for (int mi = 0; mi < 4; mi++)
#pragma unroll
        for (int ni = 0; ni < 4; ni++)
#pragma unroll
            for (int j = 0; j < 4; j++) acc[mi][ni][j] = 0.0f;

    auto load_chunk = [&](int st, int c) {
        const __half* xb = g_Xh + (size_t)m0 * D_DIM + c * BK;
        const __half* wb = g_Wch + (size_t)n0 * D_DIM + c * BK;
        uint32_t ab = sbase + (st * STAGE_HALVES) * 2;
        uint32_t bb = ab + A_HALVES * 2;
#pragma unroll
        for (int i = 0; i < 4; i++) {   // A: 128 rows x 8 segs of 8 halves
            int idx = tid + i * THREADS;
            int row = idx >> 3, seg = idx & 7;
            cp16(ab + (row * APADH + seg * 8) * 2, xb + (size_t)row * D_DIM + seg * 8);
        }
#pragma unroll
        for (int i = 0; i < 4; i++) {   // B: 128 rows x 8 segs
            int idx = tid + i * THREADS;
            int row = idx >> 3, seg = idx & 7;
            cp16(bb + (row * APADH + seg * 8) * 2, wb + (size_t)row * D_DIM + seg * 8);
        }
    };

    // prologue: chunks 0,1
#pragma unroll
    for (int s = 0; s < NST - 1; s++) {
        load_chunk(s, s);
        asm volatile("cp.async.commit_group;" ::: "memory");
    }

    const int NCHUNK = D_DIM / BK;                   // 16
    for (int c = 0; c < NCHUNK; c++) {
        const int st = c % NST;
        asm volatile("cp.async.wait_group 1;" ::: "memory");
        __syncthreads();

        const uint32_t aB = sbase + (st * STAGE_HALVES) * 2;
        const uint32_t bB = aB + A_HALVES * 2;

#pragma unroll
        for (int ks = 0; ks < 4; ks++) {             // 4 x k=16 steps
            uint32_t af[4][4];
#pragma unroll
            for (int mi = 0; mi < 4; mi++)
                ldm4(af[mi], aB + (((wm * 64 + mi * 16 + arow) * APADH)
                                   + ks * 16 + akh) * 2);
            uint32_t bf[4][2];
#pragma unroll
            for (int p = 0; p < 2; p++) {            // 2 n-pairs of 16 rows
                uint32_t r4[4];
                ldm4(r4, bB + (((wn * 32 + p * 16 + brow) * APADH)
                               + ks * 16 + bkh) * 2);
                bf[p * 2 + 0][0] = r4[0];  bf[p * 2 + 0][1] = r4[1];
                bf[p * 2 + 1][0] = r4[2];  bf[p * 2 + 1][1] = r4[3];
            }
#pragma unroll
            for (int mi = 0; mi < 4; mi++)
#pragma unroll
                for (int ni = 0; ni < 4; ni++)
                    mma16(acc[mi][ni], af[mi], bf[ni]);
        }

        // refill stage (c+2)%3 (chunk c-1's stage; compute done in all warps)
        int nc = c + NST - 1;
        if (nc < NCHUNK) load_chunk(nc % NST, nc);
        asm volatile("cp.async.commit_group;" ::: "memory");  // uniform count
    }

    // ---- epilogue: add bias, store fp32, coalesced float2
#pragma unroll
    for (int mi = 0; mi < 4; mi++) {
        int row = m0 + wm * 64 + mi * 16 + g;
        float* o0 = Out + (size_t)row * D_DIM;
        float* o1 = o0 + (size_t)8 * D_DIM;
#pragma unroll
        for (int ni = 0; ni < 4; ni++) {
            int col = n0 + wn * 32 + ni * 8 + 2 * t;
            float2 bv = *(const float2*)(bias + col);
            float2 v0, v1;
            v0.x = acc[mi][ni][0] + bv.x;  v0.y = acc[mi][ni][1] + bv.y;
            v1.x = acc[mi][ni][2] + bv.x;  v1.y = acc[mi][ni][3] + bv.y;
            *(float2*)(o0 + col) = v0;
            *(float2*)(o1 + col) = v1;
        }
    }
}

// ---------------------------------------------------------------- launch
extern "C" void kernel_launch(void* const* d_in, const int* in_sizes, int n_in,
                              void* d_out, int out_size)
{
    const float* x    = (const float*)d_in[0];  // (4,4096,1024)
    const float* Ws   = (const float*)d_in[3];  // (1024,1024)
    const float* We   = (const float*)d_in[4];  // (1024,1024)
    const float* bias = (const float*)d_in[6];  // (1024,)
    float* out = (float*)d_out;

    cudaFuncSetAttribute(moe_gemm_kernel,
                         cudaFuncAttributeMaxDynamicSharedMemorySize, SMEM_BYTES);

    // fused pre-pass: X -> fp16 (blocks 0..8191), Wc = fp16(Ws+We) (last 512)
    cvt_kernel<<<XBLOCKS + 512, 256>>>(x, Ws, We);

    // GEMM: (16384/128) m-tiles x (1024/128) n-tiles = 1024 CTAs
    moe_gemm_kernel<<<(T_DIM / BM) * (D_DIM / BN), THREADS, SMEM_BYTES>>>(bias, out);
}